// round 10
// baseline (speedup 1.0000x reference)
#include <cuda_runtime.h>
#include <cuda_fp16.h>
#include <math_constants.h>

#define HH 512
#define WW 512
#define BB 16
// window p=35, pad=17
// loss = mean(erosion_35x35(min_c x)) - 1   (erosion = separable min filter)

// Intermediate: vertically eroded field, [B][H][W/2], half2 packs (w, w+1)
__device__ __align__(16) __half2 g_t2[BB * HH * WW / 2];
// Per-block partial sums from kernel 2 (1024 blocks)
__device__ float g_partial[1024];

// ---------------------------------------------------------------------------
// Kernel 1 (UNCHANGED round-4 form — measured at the memory roofline):
// channel-min of x (fp32 -> fp16) fused with vertical min-filter,
// van Herk chunk 35, half2 packed along W.
// Block = (32 lanes, 4 chunks) = 128 thr; grid = (W/64, B, 4).
// ---------------------------------------------------------------------------
__global__ __launch_bounds__(128) void k1_vert(const float* __restrict__ x) {
    __shared__ __half2 sm[174 * 32];

    const int tx  = threadIdx.x;
    const int ty  = threadIdx.y;
    const int tid = ty * 32 + tx;
    const int wc0 = blockIdx.x * 64;
    const int b   = blockIdx.y;
    const int z   = blockIdx.z;
    const int r0  = z * 140;                 // 4 chunks * 35 rows per z-group
    const float INF = CUDART_INF_F;

    const float* xb = x + (size_t)b * 3 * HH * WW;
    for (int j = tid; j < 174 * 16; j += 128) {
        int r  = j >> 4;
        int c4 = j & 15;
        int gh = r0 - 17 + r;
        float4 m;
        if ((unsigned)gh < HH) {
            const float4* p = (const float4*)(xb + (size_t)gh * WW + wc0 + c4 * 4);
            float4 a0 = p[0];
            float4 a1 = p[(HH * WW) / 4];
            float4 a2 = p[(2 * HH * WW) / 4];
            m.x = fminf(a0.x, fminf(a1.x, a2.x));
            m.y = fminf(a0.y, fminf(a1.y, a2.y));
            m.z = fminf(a0.z, fminf(a1.z, a2.z));
            m.w = fminf(a0.w, fminf(a1.w, a2.w));
        } else {
            m = make_float4(INF, INF, INF, INF);
        }
        sm[r * 32 + c4 * 2]     = __floats2half2_rn(m.x, m.y);
        sm[r * 32 + c4 * 2 + 1] = __floats2half2_rn(m.z, m.w);
    }
    __syncthreads();

    const int c    = z * 4 + ty;
    const int base = 35 * c;
    if (base >= HH) return;
    const int lb = 35 * ty + 17;
    const __half2 HINF = __float2half2_rn(CUDART_INF_F);

    __half2 S[35];
    __half2 run = HINF;
    #pragma unroll
    for (int k = 0; k < 52; k++) {
        if (k == 35) run = HINF;
        run = __hmin2(run, sm[(lb + 34 - k) * 32 + tx]);
        if (k >= 17) S[51 - k] = run;
    }

    run = HINF;
    const size_t ob = (size_t)b * HH;
    const int wcol = (wc0 >> 1) + tx;
    #pragma unroll
    for (int k = 0; k < 52; k++) {
        if (k == 35) run = HINF;
        run = __hmin2(run, sm[(lb + k) * 32 + tx]);
        if (k >= 17) {
            int i = base + k - 17;
            if (i < HH)
                g_t2[(ob + i) * (WW / 2) + wcol] = __hmin2(S[k - 17], run);
        }
    }
}

// ---------------------------------------------------------------------------
// Kernel 2: horizontal min-filter in PAIR DOMAIN with chunk length 36
// (round-9 compute, UNCHANGED). NO fence / NO atomic / NO last-block tail:
// just write the per-block partial. grid = (H/8, B) = 1024 blocks.
// ---------------------------------------------------------------------------
__global__ __launch_bounds__(128) void k2_horiz() {
    __shared__ __half2 smt[306 * 9];          // slots: [0,18) INF | 18+pc | [274,306) INF
    __shared__ float red[128];

    const int tx  = threadIdx.x;              // chunk slot 0..15
    const int ty  = threadIdx.y;              // row-in-tile 0..7
    const int tid = ty * 16 + tx;
    const int h0  = blockIdx.x * 8;
    const int b   = blockIdx.y;
    const __half2 HINF2 = __float2half2_rn(CUDART_INF_F);

    // INF borders: pair-slots [0,18) and [274,306): 50 slots x 8 rows
    for (int j = tid; j < 400; j += 128) {
        int sl = j >> 3;                      // 0..49
        int r  = j & 7;
        int s  = (sl < 18) ? sl : (sl + 256);
        smt[s * 9 + r] = HINF2;
    }
    // Main data: 8 rows x 64 uint4, coalesced LDG.128, scattered STS.32
    {
        const uint4* src = (const uint4*)(g_t2 + ((size_t)b * HH + h0) * (WW / 2));
        #pragma unroll
        for (int i = 0; i < 4; i++) {
            int idx = tid + i * 128;          // = row*64 + uint4-slot
            int r   = idx >> 6;
            int c4  = (idx & 63) * 4;         // half2 pair index
            uint4 v = src[idx];
            smt[(c4 + 18) * 9 + r] = *(__half2*)&v.x;
            smt[(c4 + 19) * 9 + r] = *(__half2*)&v.y;
            smt[(c4 + 20) * 9 + r] = *(__half2*)&v.z;
            smt[(c4 + 21) * 9 + r] = *(__half2*)&v.w;
        }
    }
    __syncthreads();

    const int t = tx - 1;                     // -1..14 (slot 15 fully masked)

    // Backward: suffix pair-minima over chunk t (tile slots 18t+u+18)
    __half2 SR[18];
    {
        __half2 run = HINF2;
        #pragma unroll
        for (int u = 17; u >= 0; u--) {
            run = __hmin2(run, smt[(18 * t + u + 18) * 9 + ty]);
            SR[u] = run;
        }
    }

    // Forward over chunk t+1 (tile slots 18t+n+36) + combine + accumulate
    __half2 hacc = __float2half2_rn(0.0f);
    __half2 Rp  = HINF2;                      // R[n-1]
    __half2 HPp = HINF2;                      // hmin(R[n-1]) broadcast
    const int obase = 36 * t + 18;
    #pragma unroll
    for (int n = 0; n < 18; n++) {
        __half2 v  = smt[(18 * t + n + 36) * 9 + ty];
        __half2 Rc = __hmin2(Rp, v);          // R[n]
        __half2 srn = (n < 17) ? SR[n + 1] : HINF2;
        unsigned srnu = *(unsigned*)&srn;
        unsigned swp  = __byte_perm(srnu, srnu, 0x1032);
        __half2 hs = __hmin2(srn, *(__half2*)&swp);   // H_S[n+1] broadcast
        unsigned sru = *(unsigned*)&SR[n];
        unsigned Rcu = *(unsigned*)&Rc;
        unsigned Rpu = *(unsigned*)&Rp;
        unsigned HPu = *(unsigned*)&HPp;
        unsigned Au = __byte_perm(sru, Rcu, 0x5432);  // (SR[n].hi, Rc.lo)
        unsigned Bu = __byte_perm(HPu, Rpu, 0x7610);  // (HPp,      Rp.hi)
        __half2 o = __hmin2(__hmin2(*(__half2*)&Au, *(__half2*)&Bu), hs);
        if ((unsigned)(obase + 2 * n) < 512u)
            hacc = __hadd2(hacc, o);
        unsigned rs = __byte_perm(Rcu, Rcu, 0x1032);
        HPp = __hmin2(Rc, *(__half2*)&rs);    // hmin(R[n]) broadcast
        Rp = Rc;
    }
    float2 e2 = __half22float2(hacc);
    float acc = e2.x + e2.y;

    // Deterministic in-block reduction (128 threads) -> one partial per block
    red[tid] = acc;
    __syncthreads();
    #pragma unroll
    for (int s = 64; s > 0; s >>= 1) {
        if (tid < s) red[tid] += red[tid + s];
        __syncthreads();
    }
    if (tid == 0) g_partial[b * 64 + blockIdx.x] = red[0];
}

// ---------------------------------------------------------------------------
// Kernel 3: final reduction of 1024 partials; loss = mean(erosion) - 1.
// ---------------------------------------------------------------------------
__global__ void k3_final(float* __restrict__ out) {
    __shared__ float red[512];
    int tid = threadIdx.x;
    red[tid] = g_partial[tid] + g_partial[tid + 512];
    __syncthreads();
    #pragma unroll
    for (int s = 256; s > 0; s >>= 1) {
        if (tid < s) red[tid] += red[tid + s];
        __syncthreads();
    }
    if (tid == 0) out[0] = red[0] * (1.0f / 4194304.0f) - 1.0f;
}

extern "C" void kernel_launch(void* const* d_in, const int* in_sizes, int n_in,
                              void* d_out, int out_size) {
    const float* x = (const float*)d_in[0];
    float* out = (float*)d_out;

    k1_vert<<<dim3(WW / 64, BB, 4), dim3(32, 4)>>>(x);
    k2_horiz<<<dim3(HH / 8, BB), dim3(16, 8)>>>();
    k3_final<<<1, 512>>>(out);
}

// round 11
// speedup vs baseline: 1.0232x; 1.0232x over previous
#include <cuda_runtime.h>
#include <cuda_fp16.h>
#include <math_constants.h>

#define HH 512
#define WW 512
#define BB 16
// window p=35, pad=17
// loss = mean(erosion_35x35(min_c x)) - 1   (erosion = separable min filter)

// Intermediate: vertically eroded field, [B][H][W/2], half2 packs (w, w+1)
__device__ __align__(16) __half2 g_t2[BB * HH * WW / 2];
// Per-block partial sums from kernel 2 (1024 blocks)
__device__ float g_partial[1024];

// ---------------------------------------------------------------------------
// Kernel 1 (UNCHANGED round-4 form — measured at the memory roofline):
// channel-min of x (fp32 -> fp16) fused with vertical min-filter,
// van Herk chunk 35, half2 packed along W.
// Block = (32 lanes, 4 chunks) = 128 thr; grid = (W/64, B, 4).
// ---------------------------------------------------------------------------
__global__ __launch_bounds__(128) void k1_vert(const float* __restrict__ x) {
    __shared__ __half2 sm[174 * 32];

    const int tx  = threadIdx.x;
    const int ty  = threadIdx.y;
    const int tid = ty * 32 + tx;
    const int wc0 = blockIdx.x * 64;
    const int b   = blockIdx.y;
    const int z   = blockIdx.z;
    const int r0  = z * 140;                 // 4 chunks * 35 rows per z-group
    const float INF = CUDART_INF_F;

    const float* xb = x + (size_t)b * 3 * HH * WW;
    for (int j = tid; j < 174 * 16; j += 128) {
        int r  = j >> 4;
        int c4 = j & 15;
        int gh = r0 - 17 + r;
        float4 m;
        if ((unsigned)gh < HH) {
            const float4* p = (const float4*)(xb + (size_t)gh * WW + wc0 + c4 * 4);
            float4 a0 = p[0];
            float4 a1 = p[(HH * WW) / 4];
            float4 a2 = p[(2 * HH * WW) / 4];
            m.x = fminf(a0.x, fminf(a1.x, a2.x));
            m.y = fminf(a0.y, fminf(a1.y, a2.y));
            m.z = fminf(a0.z, fminf(a1.z, a2.z));
            m.w = fminf(a0.w, fminf(a1.w, a2.w));
        } else {
            m = make_float4(INF, INF, INF, INF);
        }
        sm[r * 32 + c4 * 2]     = __floats2half2_rn(m.x, m.y);
        sm[r * 32 + c4 * 2 + 1] = __floats2half2_rn(m.z, m.w);
    }
    __syncthreads();

    const int c    = z * 4 + ty;
    const int base = 35 * c;
    if (base >= HH) return;
    const int lb = 35 * ty + 17;
    const __half2 HINF = __float2half2_rn(CUDART_INF_F);

    __half2 S[35];
    __half2 run = HINF;
    #pragma unroll
    for (int k = 0; k < 52; k++) {
        if (k == 35) run = HINF;
        run = __hmin2(run, sm[(lb + 34 - k) * 32 + tx]);
        if (k >= 17) S[51 - k] = run;
    }

    run = HINF;
    const size_t ob = (size_t)b * HH;
    const int wcol = (wc0 >> 1) + tx;
    #pragma unroll
    for (int k = 0; k < 52; k++) {
        if (k == 35) run = HINF;
        run = __hmin2(run, sm[(lb + k) * 32 + tx]);
        if (k >= 17) {
            int i = base + k - 17;
            if (i < HH)
                g_t2[(ob + i) * (WW / 2) + wcol] = __hmin2(S[k - 17], run);
        }
    }
}

// ---------------------------------------------------------------------------
// Kernel 2: horizontal min-filter in PAIR DOMAIN, chunk length 36 (round-9
// math, verified) — but NO smem tile: each thread loads its two chunks with
// 18 independent predicated LDG.64 into register arrays (full MLP, one L2
// latency instead of 36 serialized LDS exposures), then pure register
// suffix/prefix/combine. Thread (tx = chunk slot 0..15, ty = row 0..7);
// grid = (H/8, B) = 1024 blocks.
// ---------------------------------------------------------------------------
__global__ __launch_bounds__(128) void k2_horiz() {
    __shared__ float red[128];

    const int tx  = threadIdx.x;              // chunk slot 0..15 (t = tx-1)
    const int ty  = threadIdx.y;              // row-in-tile 0..7
    const int tid = ty * 16 + tx;
    const int h0  = blockIdx.x * 8;
    const int b   = blockIdx.y;
    const __half2 HINF2 = __float2half2_rn(CUDART_INF_F);
    const unsigned INFU = 0x7C007C00u;

    const int t = tx - 1;                     // -1..14
    const __half2* rowp = g_t2 + (size_t)(b * HH + h0 + ty) * (WW / 2);

    // Load chunk t (pairs [18t, 18t+18)) and chunk t+1 into registers.
    // Out-of-range uint2 (2 pairs) -> +INF. (W/2 = 256 pairs, even bound.)
    __half2 ct[18], dt[18];
    #pragma unroll
    for (int j = 0; j < 9; j++) {
        int p0 = 18 * t + 2 * j;
        uint2 v = make_uint2(INFU, INFU);
        if ((unsigned)p0 < 256u) v = *(const uint2*)(rowp + p0);
        ct[2 * j]     = *(__half2*)&v.x;
        ct[2 * j + 1] = *(__half2*)&v.y;
    }
    #pragma unroll
    for (int j = 0; j < 9; j++) {
        int p0 = 18 * (t + 1) + 2 * j;
        uint2 v = make_uint2(INFU, INFU);
        if ((unsigned)p0 < 256u) v = *(const uint2*)(rowp + p0);
        dt[2 * j]     = *(__half2*)&v.x;
        dt[2 * j + 1] = *(__half2*)&v.y;
    }

    // Backward: suffix pair-minima over chunk t
    __half2 SR[18];
    {
        __half2 run = HINF2;
        #pragma unroll
        for (int u = 17; u >= 0; u--) {
            run = __hmin2(run, ct[u]);
            SR[u] = run;
        }
    }

    // Forward over chunk t+1 + parity combine + accumulate (round-9 formulas)
    __half2 hacc = __float2half2_rn(0.0f);
    __half2 Rp  = HINF2;                      // R[n-1]
    __half2 HPp = HINF2;                      // hmin(R[n-1]) broadcast
    const int obase = 36 * t + 18;
    #pragma unroll
    for (int n = 0; n < 18; n++) {
        __half2 v  = dt[n];
        __half2 Rc = __hmin2(Rp, v);          // R[n]
        __half2 srn = (n < 17) ? SR[n + 1] : HINF2;
        unsigned srnu = *(unsigned*)&srn;
        unsigned swp  = __byte_perm(srnu, srnu, 0x1032);
        __half2 hs = __hmin2(srn, *(__half2*)&swp);   // H_S[n+1] broadcast
        unsigned sru = *(unsigned*)&SR[n];
        unsigned Rcu = *(unsigned*)&Rc;
        unsigned Rpu = *(unsigned*)&Rp;
        unsigned HPu = *(unsigned*)&HPp;
        unsigned Au = __byte_perm(sru, Rcu, 0x5432);  // (SR[n].hi, Rc.lo)
        unsigned Bu = __byte_perm(HPu, Rpu, 0x7610);  // (HPp,      Rp.hi)
        __half2 o = __hmin2(__hmin2(*(__half2*)&Au, *(__half2*)&Bu), hs);
        if ((unsigned)(obase + 2 * n) < 512u)
            hacc = __hadd2(hacc, o);
        unsigned rs = __byte_perm(Rcu, Rcu, 0x1032);
        HPp = __hmin2(Rc, *(__half2*)&rs);    // hmin(R[n]) broadcast
        Rp = Rc;
    }
    float2 e2 = __half22float2(hacc);
    float acc = e2.x + e2.y;

    // Deterministic in-block reduction (128 threads) -> one partial per block
    red[tid] = acc;
    __syncthreads();
    #pragma unroll
    for (int s = 64; s > 0; s >>= 1) {
        if (tid < s) red[tid] += red[tid + s];
        __syncthreads();
    }
    if (tid == 0) g_partial[b * 64 + blockIdx.x] = red[0];
}

// ---------------------------------------------------------------------------
// Kernel 3: final reduction of 1024 partials; loss = mean(erosion) - 1.
// ---------------------------------------------------------------------------
__global__ void k3_final(float* __restrict__ out) {
    __shared__ float red[512];
    int tid = threadIdx.x;
    red[tid] = g_partial[tid] + g_partial[tid + 512];
    __syncthreads();
    #pragma unroll
    for (int s = 256; s > 0; s >>= 1) {
        if (tid < s) red[tid] += red[tid + s];
        __syncthreads();
    }
    if (tid == 0) out[0] = red[0] * (1.0f / 4194304.0f) - 1.0f;
}

extern "C" void kernel_launch(void* const* d_in, const int* in_sizes, int n_in,
                              void* d_out, int out_size) {
    const float* x = (const float*)d_in[0];
    float* out = (float*)d_out;

    k1_vert<<<dim3(WW / 64, BB, 4), dim3(32, 4)>>>(x);
    k2_horiz<<<dim3(HH / 8, BB), dim3(16, 8)>>>();
    k3_final<<<1, 512>>>(out);
}

// round 12
// speedup vs baseline: 1.1044x; 1.0793x over previous
#include <cuda_runtime.h>
#include <cuda_fp16.h>
#include <math_constants.h>

#define HH 512
#define WW 512
#define BB 16
// window p=35, pad=17
// loss = mean(erosion_35x35(min_c x)) - 1   (erosion = separable min filter)

// Intermediate: vertically eroded field, [B][H][W/2], half2 packs (w, w+1)
__device__ __align__(16) __half2 g_t2[BB * HH * WW / 2];
// Per-block partial sums from kernel 2 (1024 blocks)
__device__ float g_partial[1024];

// ---------------------------------------------------------------------------
// Kernel 1: channel-min of x (fp32 -> fp16) fused with vertical min-filter,
// van Herk chunk 35, half2 packed along W.
// Block = 256 thr (8 warps): ALL warps load the tile (doubles load-phase
// occupancy vs chain-count-limited 128); chains run on warps ty<4 only.
// grid = (W/64, B, 4) = 512 blocks -> ~28 warps/SM during load.
// ---------------------------------------------------------------------------
__global__ __launch_bounds__(256) void k1_vert(const float* __restrict__ x) {
    __shared__ __half2 sm[174 * 32];

    const int tx  = threadIdx.x;
    const int ty  = threadIdx.y;              // 0..7
    const int tid = ty * 32 + tx;
    const int wc0 = blockIdx.x * 64;
    const int b   = blockIdx.y;
    const int z   = blockIdx.z;
    const int r0  = z * 140;                 // 4 chunks * 35 rows per z-group
    const float INF = CUDART_INF_F;

    // Load channel-min into smem rows [r0-17, r0+157) with ALL 256 threads
    const float* xb = x + (size_t)b * 3 * HH * WW;
    for (int j = tid; j < 174 * 16; j += 256) {
        int r  = j >> 4;
        int c4 = j & 15;
        int gh = r0 - 17 + r;
        float4 m;
        if ((unsigned)gh < HH) {
            const float4* p = (const float4*)(xb + (size_t)gh * WW + wc0 + c4 * 4);
            float4 a0 = p[0];
            float4 a1 = p[(HH * WW) / 4];
            float4 a2 = p[(2 * HH * WW) / 4];
            m.x = fminf(a0.x, fminf(a1.x, a2.x));
            m.y = fminf(a0.y, fminf(a1.y, a2.y));
            m.z = fminf(a0.z, fminf(a1.z, a2.z));
            m.w = fminf(a0.w, fminf(a1.w, a2.w));
        } else {
            m = make_float4(INF, INF, INF, INF);
        }
        sm[r * 32 + c4 * 2]     = __floats2half2_rn(m.x, m.y);
        sm[r * 32 + c4 * 2 + 1] = __floats2half2_rn(m.z, m.w);
    }
    __syncthreads();

    // Chains: warps ty<4 only (chunk = z*4+ty); loader warps retire here.
    if (ty >= 4) return;
    const int c    = z * 4 + ty;
    const int base = 35 * c;
    if (base >= HH) return;
    const int lb = 35 * ty + 17;
    const __half2 HINF = __float2half2_rn(CUDART_INF_F);

    __half2 S[35];
    __half2 run = HINF;
    #pragma unroll
    for (int k = 0; k < 52; k++) {
        if (k == 35) run = HINF;
        run = __hmin2(run, sm[(lb + 34 - k) * 32 + tx]);
        if (k >= 17) S[51 - k] = run;
    }

    run = HINF;
    const size_t ob = (size_t)b * HH;
    const int wcol = (wc0 >> 1) + tx;
    #pragma unroll
    for (int k = 0; k < 52; k++) {
        if (k == 35) run = HINF;
        run = __hmin2(run, sm[(lb + k) * 32 + tx]);
        if (k >= 17) {
            int i = base + k - 17;
            if (i < HH)
                g_t2[(ob + i) * (WW / 2) + wcol] = __hmin2(S[k - 17], run);
        }
    }
}

// ---------------------------------------------------------------------------
// Kernel 2: horizontal min-filter in PAIR DOMAIN, chunk length 36 (verified
// round-9 math), register-resident chains: 18 independent predicated LDG.64
// per thread, then pure register suffix/prefix/combine.
// Thread (tx = chunk slot 0..15, ty = row 0..7); grid = (H/8, B).
// ---------------------------------------------------------------------------
__global__ __launch_bounds__(128) void k2_horiz() {
    __shared__ float red[128];

    const int tx  = threadIdx.x;              // chunk slot 0..15 (t = tx-1)
    const int ty  = threadIdx.y;              // row-in-tile 0..7
    const int tid = ty * 16 + tx;
    const int h0  = blockIdx.x * 8;
    const int b   = blockIdx.y;
    const __half2 HINF2 = __float2half2_rn(CUDART_INF_F);
    const unsigned INFU = 0x7C007C00u;

    const int t = tx - 1;                     // -1..14
    const __half2* rowp = g_t2 + (size_t)(b * HH + h0 + ty) * (WW / 2);

    // Load chunk t (pairs [18t, 18t+18)) and chunk t+1 into registers.
    __half2 ct[18], dt[18];
    #pragma unroll
    for (int j = 0; j < 9; j++) {
        int p0 = 18 * t + 2 * j;
        uint2 v = make_uint2(INFU, INFU);
        if ((unsigned)p0 < 256u) v = *(const uint2*)(rowp + p0);
        ct[2 * j]     = *(__half2*)&v.x;
        ct[2 * j + 1] = *(__half2*)&v.y;
    }
    #pragma unroll
    for (int j = 0; j < 9; j++) {
        int p0 = 18 * (t + 1) + 2 * j;
        uint2 v = make_uint2(INFU, INFU);
        if ((unsigned)p0 < 256u) v = *(const uint2*)(rowp + p0);
        dt[2 * j]     = *(__half2*)&v.x;
        dt[2 * j + 1] = *(__half2*)&v.y;
    }

    // Backward: suffix pair-minima over chunk t
    __half2 SR[18];
    {
        __half2 run = HINF2;
        #pragma unroll
        for (int u = 17; u >= 0; u--) {
            run = __hmin2(run, ct[u]);
            SR[u] = run;
        }
    }

    // Forward over chunk t+1 + parity combine + accumulate
    __half2 hacc = __float2half2_rn(0.0f);
    __half2 Rp  = HINF2;                      // R[n-1]
    __half2 HPp = HINF2;                      // hmin(R[n-1]) broadcast
    const int obase = 36 * t + 18;
    #pragma unroll
    for (int n = 0; n < 18; n++) {
        __half2 v  = dt[n];
        __half2 Rc = __hmin2(Rp, v);          // R[n]
        __half2 srn = (n < 17) ? SR[n + 1] : HINF2;
        unsigned srnu = *(unsigned*)&srn;
        unsigned swp  = __byte_perm(srnu, srnu, 0x1032);
        __half2 hs = __hmin2(srn, *(__half2*)&swp);   // H_S[n+1] broadcast
        unsigned sru = *(unsigned*)&SR[n];
        unsigned Rcu = *(unsigned*)&Rc;
        unsigned Rpu = *(unsigned*)&Rp;
        unsigned HPu = *(unsigned*)&HPp;
        unsigned Au = __byte_perm(sru, Rcu, 0x5432);  // (SR[n].hi, Rc.lo)
        unsigned Bu = __byte_perm(HPu, Rpu, 0x7610);  // (HPp,      Rp.hi)
        __half2 o = __hmin2(__hmin2(*(__half2*)&Au, *(__half2*)&Bu), hs);
        if ((unsigned)(obase + 2 * n) < 512u)
            hacc = __hadd2(hacc, o);
        unsigned rs = __byte_perm(Rcu, Rcu, 0x1032);
        HPp = __hmin2(Rc, *(__half2*)&rs);    // hmin(R[n]) broadcast
        Rp = Rc;
    }
    float2 e2 = __half22float2(hacc);
    float acc = e2.x + e2.y;

    // Deterministic in-block reduction -> one partial per block
    red[tid] = acc;
    __syncthreads();
    #pragma unroll
    for (int s = 64; s > 0; s >>= 1) {
        if (tid < s) red[tid] += red[tid + s];
        __syncthreads();
    }
    if (tid == 0) g_partial[b * 64 + blockIdx.x] = red[0];
}

// ---------------------------------------------------------------------------
// Kernel 3: final reduction of 1024 partials; loss = mean(erosion) - 1.
// ---------------------------------------------------------------------------
__global__ void k3_final(float* __restrict__ out) {
    __shared__ float red[512];
    int tid = threadIdx.x;
    red[tid] = g_partial[tid] + g_partial[tid + 512];
    __syncthreads();
    #pragma unroll
    for (int s = 256; s > 0; s >>= 1) {
        if (tid < s) red[tid] += red[tid + s];
        __syncthreads();
    }
    if (tid == 0) out[0] = red[0] * (1.0f / 4194304.0f) - 1.0f;
}

extern "C" void kernel_launch(void* const* d_in, const int* in_sizes, int n_in,
                              void* d_out, int out_size) {
    const float* x = (const float*)d_in[0];
    float* out = (float*)d_out;

    k1_vert<<<dim3(WW / 64, BB, 4), dim3(32, 8)>>>(x);
    k2_horiz<<<dim3(HH / 8, BB), dim3(16, 8)>>>();
    k3_final<<<1, 512>>>(out);
}